// round 5
// baseline (speedup 1.0000x reference)
#include <cuda_runtime.h>
#include <cuda_bf16.h>
#include <mma.h>

using namespace nvcuda;

#define N_NODES 512
#define HID     1024
#define MG      132          // rows of G = [Hx(128); Ip(4)]
#define MPAD    192          // padded for 96-row tiles
#define KD      4096
#define NE      16384
#define NOUT    513
#define NN      (N_NODES * N_NODES)
#define HPLEN   (N_NODES * HID)   // 524288
#define CH      16
#define CHLEN   (HPLEN / CH)      // 32768
#define RG      8
#define NRG     ((NOUT + RG - 1) / RG)   // 65

#define SPLITK  8
#define KLEN    (KD / SPLITK)     // 512
#define GM      96
#define GN      128
#define GK      32
#define NCH     (KLEN / GK)       // 16
#define SA_LD   40
#define SB_LD   136
#define GSPLIT_STRIDE (MPAD * HID)   // 196608
#define GEMM_SMEM (2 * 2 * GM * SA_LD + 2 * 2 * GK * SB_LD)  // 32768 elems
#define GEMM_SMEM_BYTES (GEMM_SMEM * 2)                       // 65536

// ---------------- scratch (device globals; no allocation allowed) ----------
__device__ float          g_G[MG * HID];
__device__ float          g_Gsplit[SPLITK * GSPLIT_STRIDE];
__device__ float          g_gs1[MG];
__device__ float          g_gs2[MG];
__device__ int            g_winner[NN];
__device__ float          g_P[N_NODES * MG];
__device__ float          g_hp[HPLEN];
__device__ float          g_partial[NOUT * CH];
__device__ unsigned int   g_amax_bits;
__device__ __nv_bfloat16  g_Whi[KD * HID];
__device__ __nv_bfloat16  g_Wlo[KD * HID];
__device__ __nv_bfloat16  g_Ahi[MPAD * KD];
__device__ __nv_bfloat16  g_Alo[MPAD * KD];

__device__ __forceinline__ void split2(float x, __nv_bfloat16& h, __nv_bfloat16& l) {
    h = __float2bfloat16(x);
    l = __float2bfloat16(x - __bfloat162float(h));
}

__device__ __forceinline__ void cp16(void* dst, const void* src) {
    unsigned int d = (unsigned int)__cvta_generic_to_shared(dst);
    asm volatile("cp.async.cg.shared.global [%0], [%1], 16;\n" :: "r"(d), "l"(src));
}
__device__ __forceinline__ void cp_commit() {
    asm volatile("cp.async.commit_group;\n");
}
template <int N>
__device__ __forceinline__ void cp_wait() {
    asm volatile("cp.async.wait_group %0;\n" :: "n"(N));
}

// ---------------- K_prep: W/A bf16 hi-lo conversion ----------------
#define NW4 (KD * HID / 4)        // 1048576
#define NA4 (MPAD * KD / 4)       // 196608
__global__ void __launch_bounds__(256) k_prep(const float* __restrict__ W,
                                              const float* __restrict__ X,
                                              const float* __restrict__ img) {
    int id = blockIdx.x * blockDim.x + threadIdx.x;
    if (id < NW4) {
        float4 w = *(const float4*)(W + (size_t)id * 4);
        __nv_bfloat16 h0, l0, h1, l1, h2, l2, h3, l3;
        split2(w.x, h0, l0); split2(w.y, h1, l1);
        split2(w.z, h2, l2); split2(w.w, h3, l3);
        __nv_bfloat162* dh = (__nv_bfloat162*)(g_Whi + (size_t)id * 4);
        __nv_bfloat162* dl = (__nv_bfloat162*)(g_Wlo + (size_t)id * 4);
        dh[0] = __nv_bfloat162(h0, h1); dh[1] = __nv_bfloat162(h2, h3);
        dl[0] = __nv_bfloat162(l0, l1); dl[1] = __nv_bfloat162(l2, l3);
    } else if (id < NW4 + NA4) {
        int i = id - NW4;
        int base = i * 4;
        int r = base >> 12;
        int j = base & 4095;
        float4 v;
        if (r < 128) {
            v = *(const float4*)(X + (size_t)r * KD + j);
        } else if (r < MG) {
            v = *(const float4*)(img + (r - 128) * 1024 + (j & 1023));
        } else {
            v = make_float4(0.f, 0.f, 0.f, 0.f);
        }
        __nv_bfloat16 h0, l0, h1, l1, h2, l2, h3, l3;
        split2(v.x, h0, l0); split2(v.y, h1, l1);
        split2(v.z, h2, l2); split2(v.w, h3, l3);
        __nv_bfloat162* dh = (__nv_bfloat162*)(g_Ahi + (size_t)base);
        __nv_bfloat162* dl = (__nv_bfloat162*)(g_Alo + (size_t)base);
        dh[0] = __nv_bfloat162(h0, h1); dh[1] = __nv_bfloat162(h2, h3);
        dl[0] = __nv_bfloat162(l0, l1); dl[1] = __nv_bfloat162(l2, l3);
    }
}

// ---------------- K1: G_split = A @ W, GM=96 x GN=128, pipelined -----------
#define SA_IDX(buf, part, row, col) ((((buf) * 2 + (part)) * GM + (row)) * SA_LD + (col))
#define SB_IDX(buf, part, row, col) (15360 + (((buf) * 2 + (part)) * GK + (row)) * SB_LD + (col))

__global__ void __launch_bounds__(256) k_gemm_bf16() {
    extern __shared__ __nv_bfloat16 smem[];

    int tid = threadIdx.x;
    int bx = blockIdx.x;      // N tile (8)
    int by = blockIdx.y;      // M tile (2)
    int bz = blockIdx.z;      // K split (8)
    int m0 = by * GM;
    int n0 = bx * GN;
    int k0 = bz * KLEN;

    int wid = tid >> 5;
    int wm = wid & 1;         // 2 warps in M (48 rows each)
    int wn = wid >> 1;        // 4 warps in N (32 cols each)

    wmma::fragment<wmma::accumulator, 16, 16, 16, float> acc[3][2];
    #pragma unroll
    for (int m = 0; m < 3; m++)
        #pragma unroll
        for (int n = 0; n < 2; n++)
            wmma::fill_fragment(acc[m][n], 0.f);

    auto load_chunk = [&](int buf, int kg) {
        #pragma unroll
        for (int i = 0; i < 3; i++) {
            int idx = tid + 256 * i;
            int part = idx / 384;
            int j = idx % 384;
            int row = j >> 2;
            int col = (j & 3) << 3;
            const __nv_bfloat16* src =
                (part ? g_Alo : g_Ahi) + (size_t)(m0 + row) * KD + kg + col;
            cp16(&smem[SA_IDX(buf, part, row, col)], src);
        }
        #pragma unroll
        for (int i = 0; i < 4; i++) {
            int idx = tid + 256 * i;
            int part = idx >> 9;
            int j = idx & 511;
            int row = j >> 4;
            int col = (j & 15) << 3;
            const __nv_bfloat16* src =
                (part ? g_Wlo : g_Whi) + (size_t)(kg + row) * HID + n0 + col;
            cp16(&smem[SB_IDX(buf, part, row, col)], src);
        }
    };

    load_chunk(0, k0);
    cp_commit();

    for (int ch = 0; ch < NCH; ch++) {
        if (ch + 1 < NCH) {
            load_chunk((ch + 1) & 1, k0 + (ch + 1) * GK);
            cp_commit();
            cp_wait<1>();
        } else {
            cp_wait<0>();
        }
        __syncthreads();
        int buf = ch & 1;
        #pragma unroll
        for (int ks = 0; ks < GK; ks += 16) {
            wmma::fragment<wmma::matrix_a, 16, 16, 16, __nv_bfloat16, wmma::row_major> afh[3], afl[3];
            #pragma unroll
            for (int m = 0; m < 3; m++) {
                wmma::load_matrix_sync(afh[m], &smem[SA_IDX(buf, 0, wm * 48 + m * 16, ks)], SA_LD);
                wmma::load_matrix_sync(afl[m], &smem[SA_IDX(buf, 1, wm * 48 + m * 16, ks)], SA_LD);
            }
            #pragma unroll
            for (int n = 0; n < 2; n++) {
                wmma::fragment<wmma::matrix_b, 16, 16, 16, __nv_bfloat16, wmma::row_major> bfh, bfl;
                wmma::load_matrix_sync(bfh, &smem[SB_IDX(buf, 0, ks, wn * 32 + n * 16)], SB_LD);
                wmma::load_matrix_sync(bfl, &smem[SB_IDX(buf, 1, ks, wn * 32 + n * 16)], SB_LD);
                #pragma unroll
                for (int m = 0; m < 3; m++) {
                    wmma::mma_sync(acc[m][n], afh[m], bfh, acc[m][n]);
                    wmma::mma_sync(acc[m][n], afl[m], bfh, acc[m][n]);
                    wmma::mma_sync(acc[m][n], afh[m], bfl, acc[m][n]);
                }
            }
        }
        __syncthreads();
    }

    #pragma unroll
    for (int m = 0; m < 3; m++) {
        #pragma unroll
        for (int n = 0; n < 2; n++) {
            float* outp = g_Gsplit + (size_t)bz * GSPLIT_STRIDE
                        + (size_t)(m0 + wm * 48 + m * 16) * HID + n0 + wn * 32 + n * 16;
            wmma::store_matrix_sync(outp, acc[m][n], HID, wmma::mem_row_major);
        }
    }
}

// ---------------- K2: split-K reduce + gs1/gs2 row dots --------------------
__global__ void __launch_bounds__(256) k_reduce_gs(const float* __restrict__ a) {
    int m = blockIdx.x;            // 0..131
    int t = threadIdx.x;           // 256
    float s1 = 0.f, s2 = 0.f;
    for (int c = t; c < HID; c += 256) {
        float s = 0.f;
        #pragma unroll
        for (int z = 0; z < SPLITK; z++)
            s += g_Gsplit[(size_t)z * GSPLIT_STRIDE + m * HID + c];
        g_G[m * HID + c] = s;
        s1 += s * a[c];
        s2 += s * a[HID + c];
    }
    __shared__ float sh1[256], sh2[256];
    sh1[t] = s1; sh2[t] = s2;
    __syncthreads();
    for (int s = 128; s > 0; s >>= 1) {
        if (t < s) { sh1[t] += sh1[t + s]; sh2[t] += sh2[t + s]; }
        __syncthreads();
    }
    if (t == 0) { g_gs1[m] = sh1[0]; g_gs2[m] = sh2[0]; }
}

// ---------------- K3: scatter winners (last edge wins) + amax --------------
__global__ void k_scatter(const int* __restrict__ er, const int* __restrict__ ec) {
    int e = blockIdx.x * blockDim.x + threadIdx.x;
    if (e < NE) atomicMax(&g_winner[er[e] * N_NODES + ec[e]], e);
}
__global__ void k_amax(const int* __restrict__ er, const int* __restrict__ ec,
                       const float* __restrict__ av) {
    int e = blockIdx.x * blockDim.x + threadIdx.x;
    if (e < NE && g_winner[er[e] * N_NODES + ec[e]] == e)
        atomicMax(&g_amax_bits, __float_as_uint(av[e]));   // av >= 0
}

// ---------------- K4: per-row softmax + new_adj + P ----------------
__global__ void __launch_bounds__(128) k_row(const float* __restrict__ adj_vals,
                                             float* __restrict__ out) {
    int r = blockIdx.x;
    int t = threadIdx.x;            // 128
    __shared__ float red[128];

    float s1r = g_gs1[r & 127] + g_gs1[128 + (r >> 7)];

    float ev[4]; int w[4];
    float lmax = -1e30f;
    #pragma unroll
    for (int j = 0; j < 4; j++) {
        int c = t + 128 * j;
        float s2c = g_gs2[c & 127] + g_gs2[128 + j];
        int ww = g_winner[r * N_NODES + c];
        w[j] = ww;
        float x = 0.f;
        if (ww >= 0) { float v = s1r + s2c; x = v > 0.f ? v : 0.2f * v; }
        ev[j] = x;
        lmax = fmaxf(lmax, x);
    }
    red[t] = lmax; __syncthreads();
    for (int s = 64; s > 0; s >>= 1) {
        if (t < s) red[t] = fmaxf(red[t], red[t + s]);
        __syncthreads();
    }
    float rmax = red[0]; __syncthreads();

    float ex[4]; float lsum = 0.f;
    #pragma unroll
    for (int j = 0; j < 4; j++) { ex[j] = expf(ev[j] - rmax); lsum += ex[j]; }
    red[t] = lsum; __syncthreads();
    for (int s = 64; s > 0; s >>= 1) {
        if (t < s) red[t] += red[t + s];
        __syncthreads();
    }
    float inv = 1.f / red[0]; __syncthreads();

    float amax2 = 2.f * __uint_as_float(g_amax_bits);
    float invA = amax2 > 0.f ? 1.f / amax2 : 0.f;

    float attj[4]; float pm = 0.f;
    #pragma unroll
    for (int j = 0; j < 4; j++) {
        float att = ex[j] * inv;
        attj[j] = att;
        float adjn = (w[j] >= 0) ? (2.f * adj_vals[w[j]]) * invA : 0.f;
        out[r * N_NODES + t + 128 * j] = att * adjn;
        pm += att;
    }
    g_P[r * MG + t] = pm;          // c & 127 == t for all 4 cols

    #pragma unroll
    for (int j = 0; j < 4; j++) {  // column-block sums -> P[r, 128+j]
        red[t] = attj[j]; __syncthreads();
        for (int s = 64; s > 0; s >>= 1) {
            if (t < s) red[t] += red[t + s];
            __syncthreads();
        }
        if (t == 0) g_P[r * MG + 128 + j] = red[0];
        __syncthreads();
    }
}

// ---------------- K5: hp = P(512,132) @ G(132,1024) ----------------
__global__ void __launch_bounds__(256) k_hp() {
    __shared__ float Ps[32][MG];
    __shared__ float Gs[MG][32];
    int bx = blockIdx.x;            // col tile (32)
    int by = blockIdx.y;            // row tile (16)
    int tid = threadIdx.x;

    for (int i = tid; i < 32 * MG; i += 256) {
        int rr = i / MG, kk = i % MG;
        Ps[rr][kk] = g_P[(by * 32 + rr) * MG + kk];
    }
    for (int i = tid; i < MG * 32; i += 256) {
        int kk = i / 32, cc = i % 32;
        Gs[kk][cc] = g_G[kk * HID + bx * 32 + cc];
    }
    __syncthreads();

    int tx = tid & 7, ty = tid >> 3;   // ty: row 0..31, tx: col4 0..7
    float4 acc = make_float4(0.f, 0.f, 0.f, 0.f);
    #pragma unroll 4
    for (int k = 0; k < MG; k++) {
        float p = Ps[ty][k];
        float4 gv = *(float4*)&Gs[k][tx * 4];
        acc.x += p * gv.x; acc.y += p * gv.y;
        acc.z += p * gv.z; acc.w += p * gv.w;
    }
    int row = by * 32 + ty, col = bx * 32 + tx * 4;
    *(float4*)&g_hp[row * HID + col] = acc;
}

// ---------------- K6: gemv, RG rows per block, hp reused in registers ------
__global__ void __launch_bounds__(256) k_gemv(const float* __restrict__ lin_w) {
    int chunk = blockIdx.x;          // 0..CH-1
    int rg = blockIdx.y;             // 0..NRG-1
    int t = threadIdx.x;             // 256
    int row0 = rg * RG;

    const float4* vp = (const float4*)(g_hp + (size_t)chunk * CHLEN);
    const float4* wp[RG];
    #pragma unroll
    for (int r = 0; r < RG; r++) {
        int row = row0 + r;
        if (row > NOUT - 1) row = NOUT - 1;   // clamp (loads valid, store masked)
        wp[r] = (const float4*)(lin_w + (size_t)row * HPLEN + (size_t)chunk * CHLEN);
    }

    float acc[RG] = {};
    #pragma unroll 2
    for (int i = t; i < CHLEN / 4; i += 256) {
        float4 v = __ldg(&vp[i]);
        #pragma unroll
        for (int r = 0; r < RG; r++) {
            float4 w = __ldcs(&wp[r][i]);
            acc[r] += w.x * v.x + w.y * v.y + w.z * v.z + w.w * v.w;
        }
    }

    __shared__ float sh[RG][256];
    #pragma unroll
    for (int r = 0; r < RG; r++) sh[r][t] = acc[r];
    __syncthreads();
    for (int s = 128; s > 0; s >>= 1) {
        if (t < s) {
            #pragma unroll
            for (int r = 0; r < RG; r++) sh[r][t] += sh[r][t + s];
        }
        __syncthreads();
    }
    if (t < RG) {
        int row = row0 + t;
        if (row < NOUT) g_partial[row * CH + chunk] = sh[t][0];
    }
}

// ---------------- K7: finalize + min/max normalize ----------------
__global__ void k_final(const float* __restrict__ lin_b, float* __restrict__ out) {
    __shared__ float vals[NOUT];
    __shared__ float smin[256], smax[256];
    int t = threadIdx.x;            // 256
    for (int i = t; i < NOUT; i += 256) {
        float s = lin_b[i];
        #pragma unroll
        for (int c = 0; c < CH; c++) s += g_partial[i * CH + c];
        vals[i] = s;
    }
    __syncthreads();
    float mn = 1e30f, mx = -1e30f;
    for (int i = t; i < NOUT; i += 256) {
        mn = fminf(mn, vals[i]);
        mx = fmaxf(mx, vals[i]);
    }
    smin[t] = mn; smax[t] = mx; __syncthreads();
    for (int s = 128; s > 0; s >>= 1) {
        if (t < s) {
            smin[t] = fminf(smin[t], smin[t + s]);
            smax[t] = fmaxf(smax[t], smax[t + s]);
        }
        __syncthreads();
    }
    float gmn = smin[0], gmx = smax[0];
    float denom = gmx - gmn;
    for (int i = t; i < NOUT; i += 256)
        out[NN + i] = (denom == 0.f) ? 0.5f : (vals[i] - gmn) / denom;
}

// ---------------- launch ----------------
extern "C" void kernel_launch(void* const* d_in, const int* in_sizes, int n_in,
                              void* d_out, int out_size) {
    const float* img = (const float*)d_in[0];
    const int*   er  = (const int*)d_in[1];
    const int*   ec  = (const int*)d_in[2];
    const float* av  = (const float*)d_in[3];
    const float* X   = (const float*)d_in[4];
    const float* W   = (const float*)d_in[5];
    const float* a   = (const float*)d_in[6];
    const float* lw  = (const float*)d_in[7];
    const float* lb  = (const float*)d_in[8];
    float* out = (float*)d_out;

    static cudaStream_t s2 = []() {
        cudaStream_t s; cudaStreamCreateWithFlags(&s, cudaStreamNonBlocking); return s;
    }();
    static cudaEvent_t e0 = []() {
        cudaEvent_t e; cudaEventCreateWithFlags(&e, cudaEventDisableTiming); return e;
    }();
    static cudaEvent_t e1 = []() {
        cudaEvent_t e; cudaEventCreateWithFlags(&e, cudaEventDisableTiming); return e;
    }();
    static bool attr_set = []() {
        cudaFuncSetAttribute(k_gemm_bf16, cudaFuncAttributeMaxDynamicSharedMemorySize,
                             GEMM_SMEM_BYTES);
        return true;
    }();
    (void)attr_set;

    void* winner_ptr = nullptr;
    void* amax_ptr = nullptr;
    cudaGetSymbolAddress(&winner_ptr, g_winner);
    cudaGetSymbolAddress(&amax_ptr, g_amax_bits);

    // fork: edge path on s2
    cudaEventRecord(e0, 0);
    cudaStreamWaitEvent(s2, e0, 0);
    cudaMemsetAsync(winner_ptr, 0xFF, NN * sizeof(int), s2);        // winner = -1
    cudaMemsetAsync(amax_ptr, 0x00, sizeof(unsigned int), s2);      // amax = 0
    k_scatter<<<64, 256, 0, s2>>>(er, ec);
    k_amax<<<64, 256, 0, s2>>>(er, ec, av);
    cudaEventRecord(e1, s2);

    // main path on default stream
    int prep_blocks = (NW4 + NA4 + 255) / 256;
    k_prep<<<prep_blocks, 256>>>(W, X, img);
    dim3 g1(8, 2, 8);
    k_gemm_bf16<<<g1, 256, GEMM_SMEM_BYTES>>>();
    k_reduce_gs<<<MG, 256>>>(a);

    // join
    cudaStreamWaitEvent(0, e1, 0);
    k_row<<<512, 128>>>(av, out);
    dim3 g5(32, 16);
    k_hp<<<g5, 256>>>();
    dim3 g6(CH, NRG);
    k_gemv<<<g6, 256>>>(lw);
    k_final<<<1, 256>>>(lb, out);
}

// round 6
// speedup vs baseline: 1.0350x; 1.0350x over previous
#include <cuda_runtime.h>
#include <cuda_bf16.h>
#include <mma.h>

using namespace nvcuda;

#define N_NODES 512
#define HID     1024
#define MG      132          // rows of G = [Hx(128); Ip(4)]
#define MPAD    192          // padded for 96-row tiles
#define KD      4096
#define NE      16384
#define NOUT    513
#define NN      (N_NODES * N_NODES)
#define HPLEN   (N_NODES * HID)   // 524288
#define CH      16
#define CHLEN   (HPLEN / CH)      // 32768

#define SPLITK  16
#define KLEN    (KD / SPLITK)     // 256
#define GM      96
#define GN      128
#define GK      32
#define NCH     (KLEN / GK)       // 8
#define SA_LD   40
#define SB_LD   136
#define GSPLIT_STRIDE (MPAD * HID)   // 196608
#define GEMM_SMEM (2 * 2 * GM * SA_LD + 2 * 2 * GK * SB_LD)  // 32768 elems
#define GEMM_SMEM_BYTES (GEMM_SMEM * 2)                       // 65536

// ---------------- scratch (device globals; no allocation allowed) ----------
__device__ float          g_G[MG * HID];
__device__ float          g_Gsplit[SPLITK * GSPLIT_STRIDE];
__device__ float          g_gs1[MG];
__device__ float          g_gs2[MG];
__device__ int            g_winner[NN];
__device__ float          g_P[N_NODES * MG];
__device__ float          g_hp[HPLEN];
__device__ float          g_partial[NOUT * CH];
__device__ unsigned int   g_amax_bits;
__device__ __nv_bfloat16  g_Whi[KD * HID];
__device__ __nv_bfloat16  g_Wlo[KD * HID];
__device__ __nv_bfloat16  g_Ahi[MPAD * KD];
__device__ __nv_bfloat16  g_Alo[MPAD * KD];

__device__ __forceinline__ void split2(float x, __nv_bfloat16& h, __nv_bfloat16& l) {
    h = __float2bfloat16(x);
    l = __float2bfloat16(x - __bfloat162float(h));
}

__device__ __forceinline__ void cp16(void* dst, const void* src) {
    unsigned int d = (unsigned int)__cvta_generic_to_shared(dst);
    asm volatile("cp.async.cg.shared.global [%0], [%1], 16;\n" :: "r"(d), "l"(src));
}
__device__ __forceinline__ void cp_commit() {
    asm volatile("cp.async.commit_group;\n");
}
template <int N>
__device__ __forceinline__ void cp_wait() {
    asm volatile("cp.async.wait_group %0;\n" :: "n"(N));
}

// ---------------- K_prep: W/A bf16 hi-lo conversion ----------------
#define NW4 (KD * HID / 4)        // 1048576
#define NA4 (MPAD * KD / 4)       // 196608
__global__ void __launch_bounds__(256) k_prep(const float* __restrict__ W,
                                              const float* __restrict__ X,
                                              const float* __restrict__ img) {
    int id = blockIdx.x * blockDim.x + threadIdx.x;
    if (id < NW4) {
        float4 w = *(const float4*)(W + (size_t)id * 4);
        __nv_bfloat16 h0, l0, h1, l1, h2, l2, h3, l3;
        split2(w.x, h0, l0); split2(w.y, h1, l1);
        split2(w.z, h2, l2); split2(w.w, h3, l3);
        __nv_bfloat162* dh = (__nv_bfloat162*)(g_Whi + (size_t)id * 4);
        __nv_bfloat162* dl = (__nv_bfloat162*)(g_Wlo + (size_t)id * 4);
        dh[0] = __nv_bfloat162(h0, h1); dh[1] = __nv_bfloat162(h2, h3);
        dl[0] = __nv_bfloat162(l0, l1); dl[1] = __nv_bfloat162(l2, l3);
    } else if (id < NW4 + NA4) {
        int i = id - NW4;
        int base = i * 4;
        int r = base >> 12;
        int j = base & 4095;
        float4 v;
        if (r < 128) {
            v = *(const float4*)(X + (size_t)r * KD + j);
        } else if (r < MG) {
            v = *(const float4*)(img + (r - 128) * 1024 + (j & 1023));
        } else {
            v = make_float4(0.f, 0.f, 0.f, 0.f);
        }
        __nv_bfloat16 h0, l0, h1, l1, h2, l2, h3, l3;
        split2(v.x, h0, l0); split2(v.y, h1, l1);
        split2(v.z, h2, l2); split2(v.w, h3, l3);
        __nv_bfloat162* dh = (__nv_bfloat162*)(g_Ahi + (size_t)base);
        __nv_bfloat162* dl = (__nv_bfloat162*)(g_Alo + (size_t)base);
        dh[0] = __nv_bfloat162(h0, h1); dh[1] = __nv_bfloat162(h2, h3);
        dl[0] = __nv_bfloat162(l0, l1); dl[1] = __nv_bfloat162(l2, l3);
    }
}

// ---------------- K1: G_split = A @ W, GM=96 x GN=128, pipelined -----------
#define SA_IDX(buf, part, row, col) ((((buf) * 2 + (part)) * GM + (row)) * SA_LD + (col))
#define SB_IDX(buf, part, row, col) (15360 + (((buf) * 2 + (part)) * GK + (row)) * SB_LD + (col))

__global__ void __launch_bounds__(256, 2) k_gemm_bf16() {
    extern __shared__ __nv_bfloat16 smem[];

    int tid = threadIdx.x;
    int bx = blockIdx.x;      // N tile (8)
    int by = blockIdx.y;      // M tile (2)
    int bz = blockIdx.z;      // K split (16)
    int m0 = by * GM;
    int n0 = bx * GN;
    int k0 = bz * KLEN;

    int wid = tid >> 5;
    int wm = wid & 1;         // 2 warps in M (48 rows each)
    int wn = wid >> 1;        // 4 warps in N (32 cols each)

    wmma::fragment<wmma::accumulator, 16, 16, 16, float> acc[3][2];
    #pragma unroll
    for (int m = 0; m < 3; m++)
        #pragma unroll
        for (int n = 0; n < 2; n++)
            wmma::fill_fragment(acc[m][n], 0.f);

    auto load_chunk = [&](int buf, int kg) {
        #pragma unroll
        for (int i = 0; i < 3; i++) {
            int idx = tid + 256 * i;
            int part = idx / 384;
            int j = idx % 384;
            int row = j >> 2;
            int col = (j & 3) << 3;
            const __nv_bfloat16* src =
                (part ? g_Alo : g_Ahi) + (size_t)(m0 + row) * KD + kg + col;
            cp16(&smem[SA_IDX(buf, part, row, col)], src);
        }
        #pragma unroll
        for (int i = 0; i < 4; i++) {
            int idx = tid + 256 * i;
            int part = idx >> 9;
            int j = idx & 511;
            int row = j >> 4;
            int col = (j & 15) << 3;
            const __nv_bfloat16* src =
                (part ? g_Wlo : g_Whi) + (size_t)(kg + row) * HID + n0 + col;
            cp16(&smem[SB_IDX(buf, part, row, col)], src);
        }
    };

    load_chunk(0, k0);
    cp_commit();

    for (int ch = 0; ch < NCH; ch++) {
        if (ch + 1 < NCH) {
            load_chunk((ch + 1) & 1, k0 + (ch + 1) * GK);
            cp_commit();
            cp_wait<1>();
        } else {
            cp_wait<0>();
        }
        __syncthreads();
        int buf = ch & 1;
        #pragma unroll
        for (int ks = 0; ks < GK; ks += 16) {
            wmma::fragment<wmma::matrix_a, 16, 16, 16, __nv_bfloat16, wmma::row_major> afh[3], afl[3];
            #pragma unroll
            for (int m = 0; m < 3; m++) {
                wmma::load_matrix_sync(afh[m], &smem[SA_IDX(buf, 0, wm * 48 + m * 16, ks)], SA_LD);
                wmma::load_matrix_sync(afl[m], &smem[SA_IDX(buf, 1, wm * 48 + m * 16, ks)], SA_LD);
            }
            #pragma unroll
            for (int n = 0; n < 2; n++) {
                wmma::fragment<wmma::matrix_b, 16, 16, 16, __nv_bfloat16, wmma::row_major> bfh, bfl;
                wmma::load_matrix_sync(bfh, &smem[SB_IDX(buf, 0, ks, wn * 32 + n * 16)], SB_LD);
                wmma::load_matrix_sync(bfl, &smem[SB_IDX(buf, 1, ks, wn * 32 + n * 16)], SB_LD);
                #pragma unroll
                for (int m = 0; m < 3; m++) {
                    wmma::mma_sync(acc[m][n], afh[m], bfh, acc[m][n]);
                    wmma::mma_sync(acc[m][n], afl[m], bfh, acc[m][n]);
                    wmma::mma_sync(acc[m][n], afh[m], bfl, acc[m][n]);
                }
            }
        }
        __syncthreads();
    }

    #pragma unroll
    for (int m = 0; m < 3; m++) {
        #pragma unroll
        for (int n = 0; n < 2; n++) {
            float* outp = g_Gsplit + (size_t)bz * GSPLIT_STRIDE
                        + (size_t)(m0 + wm * 48 + m * 16) * HID + n0 + wn * 32 + n * 16;
            wmma::store_matrix_sync(outp, acc[m][n], HID, wmma::mem_row_major);
        }
    }
}

// ---------------- K2: split-K reduce + gs1/gs2 row dots --------------------
__global__ void __launch_bounds__(256) k_reduce_gs(const float* __restrict__ a) {
    int m = blockIdx.x;            // 0..131
    int t = threadIdx.x;           // 256
    float s1 = 0.f, s2 = 0.f;
    for (int c = t; c < HID; c += 256) {
        float s = 0.f;
        #pragma unroll
        for (int z = 0; z < SPLITK; z++)
            s += g_Gsplit[(size_t)z * GSPLIT_STRIDE + m * HID + c];
        g_G[m * HID + c] = s;
        s1 += s * a[c];
        s2 += s * a[HID + c];
    }
    __shared__ float sh1[256], sh2[256];
    sh1[t] = s1; sh2[t] = s2;
    __syncthreads();
    for (int s = 128; s > 0; s >>= 1) {
        if (t < s) { sh1[t] += sh1[t + s]; sh2[t] += sh2[t + s]; }
        __syncthreads();
    }
    if (t == 0) { g_gs1[m] = sh1[0]; g_gs2[m] = sh2[0]; }
}

// ---------------- K3: scatter winners (last edge wins) + amax --------------
__global__ void k_scatter(const int* __restrict__ er, const int* __restrict__ ec) {
    int e = blockIdx.x * blockDim.x + threadIdx.x;
    if (e < NE) atomicMax(&g_winner[er[e] * N_NODES + ec[e]], e);
}
__global__ void k_amax(const int* __restrict__ er, const int* __restrict__ ec,
                       const float* __restrict__ av) {
    int e = blockIdx.x * blockDim.x + threadIdx.x;
    if (e < NE && g_winner[er[e] * N_NODES + ec[e]] == e)
        atomicMax(&g_amax_bits, __float_as_uint(av[e]));   // av >= 0
}

// ---------------- K4: per-row softmax + new_adj + P ----------------
__global__ void __launch_bounds__(128) k_row(const float* __restrict__ adj_vals,
                                             float* __restrict__ out) {
    int r = blockIdx.x;
    int t = threadIdx.x;            // 128
    __shared__ float red[128];

    float s1r = g_gs1[r & 127] + g_gs1[128 + (r >> 7)];

    float ev[4]; int w[4];
    float lmax = -1e30f;
    #pragma unroll
    for (int j = 0; j < 4; j++) {
        int c = t + 128 * j;
        float s2c = g_gs2[c & 127] + g_gs2[128 + j];
        int ww = g_winner[r * N_NODES + c];
        w[j] = ww;
        float x = 0.f;
        if (ww >= 0) { float v = s1r + s2c; x = v > 0.f ? v : 0.2f * v; }
        ev[j] = x;
        lmax = fmaxf(lmax, x);
    }
    red[t] = lmax; __syncthreads();
    for (int s = 64; s > 0; s >>= 1) {
        if (t < s) red[t] = fmaxf(red[t], red[t + s]);
        __syncthreads();
    }
    float rmax = red[0]; __syncthreads();

    float ex[4]; float lsum = 0.f;
    #pragma unroll
    for (int j = 0; j < 4; j++) { ex[j] = expf(ev[j] - rmax); lsum += ex[j]; }
    red[t] = lsum; __syncthreads();
    for (int s = 64; s > 0; s >>= 1) {
        if (t < s) red[t] += red[t + s];
        __syncthreads();
    }
    float inv = 1.f / red[0]; __syncthreads();

    float amax2 = 2.f * __uint_as_float(g_amax_bits);
    float invA = amax2 > 0.f ? 1.f / amax2 : 0.f;

    float attj[4]; float pm = 0.f;
    #pragma unroll
    for (int j = 0; j < 4; j++) {
        float att = ex[j] * inv;
        attj[j] = att;
        float adjn = (w[j] >= 0) ? (2.f * adj_vals[w[j]]) * invA : 0.f;
        out[r * N_NODES + t + 128 * j] = att * adjn;
        pm += att;
    }
    g_P[r * MG + t] = pm;          // c & 127 == t for all 4 cols

    #pragma unroll
    for (int j = 0; j < 4; j++) {  // column-block sums -> P[r, 128+j]
        red[t] = attj[j]; __syncthreads();
        for (int s = 64; s > 0; s >>= 1) {
            if (t < s) red[t] += red[t + s];
            __syncthreads();
        }
        if (t == 0) g_P[r * MG + 128 + j] = red[0];
        __syncthreads();
    }
}

// ---------------- K5: hp = P(512,132) @ G(132,1024) ----------------
__global__ void __launch_bounds__(256) k_hp() {
    __shared__ float Ps[32][MG];
    __shared__ float Gs[MG][32];
    int bx = blockIdx.x;            // col tile (32)
    int by = blockIdx.y;            // row tile (16)
    int tid = threadIdx.x;

    for (int i = tid; i < 32 * MG; i += 256) {
        int rr = i / MG, kk = i % MG;
        Ps[rr][kk] = g_P[(by * 32 + rr) * MG + kk];
    }
    for (int i = tid; i < MG * 32; i += 256) {
        int kk = i / 32, cc = i % 32;
        Gs[kk][cc] = g_G[kk * HID + bx * 32 + cc];
    }
    __syncthreads();

    int tx = tid & 7, ty = tid >> 3;   // ty: row 0..31, tx: col4 0..7
    float4 acc = make_float4(0.f, 0.f, 0.f, 0.f);
    #pragma unroll 4
    for (int k = 0; k < MG; k++) {
        float p = Ps[ty][k];
        float4 gv = *(float4*)&Gs[k][tx * 4];
        acc.x += p * gv.x; acc.y += p * gv.y;
        acc.z += p * gv.z; acc.w += p * gv.w;
    }
    int row = by * 32 + ty, col = bx * 32 + tx * 4;
    *(float4*)&g_hp[row * HID + col] = acc;
}

// ---------------- K6: out_partial = lin_w(513,524288) @ hp (R4 version) ----
__global__ void __launch_bounds__(256) k_gemv(const float* __restrict__ lin_w) {
    int chunk = blockIdx.x;
    int row = blockIdx.y;
    int t = threadIdx.x;            // 256
    const float4* wp = (const float4*)(lin_w + (size_t)row * HPLEN + (size_t)chunk * CHLEN);
    const float4* vp = (const float4*)(g_hp + (size_t)chunk * CHLEN);
    float acc = 0.f;
    #pragma unroll 8
    for (int i = t; i < CHLEN / 4; i += 256) {
        float4 w4 = __ldcs(&wp[i]);
        float4 v4 = __ldg(&vp[i]);
        acc += w4.x * v4.x + w4.y * v4.y + w4.z * v4.z + w4.w * v4.w;
    }
    __shared__ float sh[256];
    sh[t] = acc; __syncthreads();
    for (int s = 128; s > 0; s >>= 1) {
        if (t < s) sh[t] += sh[t + s];
        __syncthreads();
    }
    if (t == 0) g_partial[row * CH + chunk] = sh[0];
}

// ---------------- K7: finalize + min/max normalize ----------------
__global__ void k_final(const float* __restrict__ lin_b, float* __restrict__ out) {
    __shared__ float vals[NOUT];
    __shared__ float smin[256], smax[256];
    int t = threadIdx.x;            // 256
    for (int i = t; i < NOUT; i += 256) {
        float s = lin_b[i];
        #pragma unroll
        for (int c = 0; c < CH; c++) s += g_partial[i * CH + c];
        vals[i] = s;
    }
    __syncthreads();
    float mn = 1e30f, mx = -1e30f;
    for (int i = t; i < NOUT; i += 256) {
        mn = fminf(mn, vals[i]);
        mx = fmaxf(mx, vals[i]);
    }
    smin[t] = mn; smax[t] = mx; __syncthreads();
    for (int s = 128; s > 0; s >>= 1) {
        if (t < s) {
            smin[t] = fminf(smin[t], smin[t + s]);
            smax[t] = fmaxf(smax[t], smax[t + s]);
        }
        __syncthreads();
    }
    float gmn = smin[0], gmx = smax[0];
    float denom = gmx - gmn;
    for (int i = t; i < NOUT; i += 256)
        out[NN + i] = (denom == 0.f) ? 0.5f : (vals[i] - gmn) / denom;
}

// ---------------- launch ----------------
extern "C" void kernel_launch(void* const* d_in, const int* in_sizes, int n_in,
                              void* d_out, int out_size) {
    const float* img = (const float*)d_in[0];
    const int*   er  = (const int*)d_in[1];
    const int*   ec  = (const int*)d_in[2];
    const float* av  = (const float*)d_in[3];
    const float* X   = (const float*)d_in[4];
    const float* W   = (const float*)d_in[5];
    const float* a   = (const float*)d_in[6];
    const float* lw  = (const float*)d_in[7];
    const float* lb  = (const float*)d_in[8];
    float* out = (float*)d_out;

    static cudaStream_t s2 = []() {
        cudaStream_t s; cudaStreamCreateWithFlags(&s, cudaStreamNonBlocking); return s;
    }();
    static cudaEvent_t e0 = []() {
        cudaEvent_t e; cudaEventCreateWithFlags(&e, cudaEventDisableTiming); return e;
    }();
    static cudaEvent_t e1 = []() {
        cudaEvent_t e; cudaEventCreateWithFlags(&e, cudaEventDisableTiming); return e;
    }();
    static bool attr_set = []() {
        cudaFuncSetAttribute(k_gemm_bf16, cudaFuncAttributeMaxDynamicSharedMemorySize,
                             GEMM_SMEM_BYTES);
        return true;
    }();
    (void)attr_set;

    void* winner_ptr = nullptr;
    void* amax_ptr = nullptr;
    cudaGetSymbolAddress(&winner_ptr, g_winner);
    cudaGetSymbolAddress(&amax_ptr, g_amax_bits);

    // fork: edge path on s2
    cudaEventRecord(e0, 0);
    cudaStreamWaitEvent(s2, e0, 0);
    cudaMemsetAsync(winner_ptr, 0xFF, NN * sizeof(int), s2);        // winner = -1
    cudaMemsetAsync(amax_ptr, 0x00, sizeof(unsigned int), s2);      // amax = 0
    k_scatter<<<64, 256, 0, s2>>>(er, ec);
    k_amax<<<64, 256, 0, s2>>>(er, ec, av);
    cudaEventRecord(e1, s2);

    // main path on default stream
    int prep_blocks = (NW4 + NA4 + 255) / 256;
    k_prep<<<prep_blocks, 256>>>(W, X, img);
    dim3 g1(8, 2, SPLITK);
    k_gemm_bf16<<<g1, 256, GEMM_SMEM_BYTES>>>();
    k_reduce_gs<<<MG, 256>>>(a);

    // join
    cudaStreamWaitEvent(0, e1, 0);
    k_row<<<512, 128>>>(av, out);
    dim3 g5(32, 16);
    k_hp<<<g5, 256>>>();
    dim3 g6(CH, NOUT);
    k_gemv<<<g6, 256>>>(lw);
    k_final<<<1, 256>>>(lb, out);
}

// round 7
// speedup vs baseline: 1.0584x; 1.0226x over previous
#include <cuda_runtime.h>
#include <cuda_bf16.h>
#include <mma.h>

using namespace nvcuda;

#define N_NODES 512
#define HID     1024
#define MG      132          // rows of G = [Hx(128); Ip(4)]
#define MPAD    144          // padded for 48-row tiles
#define KD      4096
#define NE      16384
#define NOUT    513
#define NN      (N_NODES * N_NODES)
#define HPLEN   (N_NODES * HID)   // 524288
#define CH      16
#define CHLEN   (HPLEN / CH)      // 32768
#define RG      2
#define NRG     ((NOUT + RG - 1) / RG)   // 257

#define SPLITK  16
#define KLEN    (KD / SPLITK)     // 256
#define GM      48
#define GN      128
#define GK      32
#define NCH     (KLEN / GK)       // 8
#define SA_LD   40
#define SB_LD   136
#define GSPLIT_STRIDE (MPAD * HID)   // 147456
// smem (bf16 elems): A = 2buf*2part*48*40 = 7680 ; B = 2buf*2part*32*136 = 17408
#define SB_BASE 7680
#define GEMM_SMEM (7680 + 17408)          // 25088 elems
#define GEMM_SMEM_BYTES (GEMM_SMEM * 2)   // 50176

// ---------------- scratch (device globals; no allocation allowed) ----------
__device__ float          g_G[MG * HID];
__device__ float          g_Gsplit[SPLITK * GSPLIT_STRIDE];
__device__ float          g_gs1[MG];
__device__ float          g_gs2[MG];
__device__ int            g_winner[NN];
__device__ float          g_P[N_NODES * MG];
__device__ float          g_hp[HPLEN];
__device__ float          g_partial[NOUT * CH];
__device__ unsigned int   g_amax_bits;
__device__ __nv_bfloat16  g_Whi[KD * HID];
__device__ __nv_bfloat16  g_Wlo[KD * HID];
__device__ __nv_bfloat16  g_Ahi[MPAD * KD];
__device__ __nv_bfloat16  g_Alo[MPAD * KD];

__device__ __forceinline__ void split2(float x, __nv_bfloat16& h, __nv_bfloat16& l) {
    h = __float2bfloat16(x);
    l = __float2bfloat16(x - __bfloat162float(h));
}

__device__ __forceinline__ void cp16(void* dst, const void* src) {
    unsigned int d = (unsigned int)__cvta_generic_to_shared(dst);
    asm volatile("cp.async.cg.shared.global [%0], [%1], 16;\n" :: "r"(d), "l"(src));
}
__device__ __forceinline__ void cp_commit() {
    asm volatile("cp.async.commit_group;\n");
}
template <int N>
__device__ __forceinline__ void cp_wait() {
    asm volatile("cp.async.wait_group %0;\n" :: "n"(N));
}

// ---------------- K_prep: W/A bf16 hi-lo conversion ----------------
#define NW4 (KD * HID / 4)        // 1048576
#define NA4 (MPAD * KD / 4)       // 147456
__global__ void __launch_bounds__(256) k_prep(const float* __restrict__ W,
                                              const float* __restrict__ X,
                                              const float* __restrict__ img) {
    int id = blockIdx.x * blockDim.x + threadIdx.x;
    if (id < NW4) {
        float4 w = *(const float4*)(W + (size_t)id * 4);
        __nv_bfloat16 h0, l0, h1, l1, h2, l2, h3, l3;
        split2(w.x, h0, l0); split2(w.y, h1, l1);
        split2(w.z, h2, l2); split2(w.w, h3, l3);
        __nv_bfloat162* dh = (__nv_bfloat162*)(g_Whi + (size_t)id * 4);
        __nv_bfloat162* dl = (__nv_bfloat162*)(g_Wlo + (size_t)id * 4);
        dh[0] = __nv_bfloat162(h0, h1); dh[1] = __nv_bfloat162(h2, h3);
        dl[0] = __nv_bfloat162(l0, l1); dl[1] = __nv_bfloat162(l2, l3);
    } else if (id < NW4 + NA4) {
        int i = id - NW4;
        int base = i * 4;
        int r = base >> 12;
        int j = base & 4095;
        float4 v;
        if (r < 128) {
            v = *(const float4*)(X + (size_t)r * KD + j);
        } else if (r < MG) {
            v = *(const float4*)(img + (r - 128) * 1024 + (j & 1023));
        } else {
            v = make_float4(0.f, 0.f, 0.f, 0.f);
        }
        __nv_bfloat16 h0, l0, h1, l1, h2, l2, h3, l3;
        split2(v.x, h0, l0); split2(v.y, h1, l1);
        split2(v.z, h2, l2); split2(v.w, h3, l3);
        __nv_bfloat162* dh = (__nv_bfloat162*)(g_Ahi + (size_t)base);
        __nv_bfloat162* dl = (__nv_bfloat162*)(g_Alo + (size_t)base);
        dh[0] = __nv_bfloat162(h0, h1); dh[1] = __nv_bfloat162(h2, h3);
        dl[0] = __nv_bfloat162(l0, l1); dl[1] = __nv_bfloat162(l2, l3);
    }
}

// ---------------- K1: G_split = A @ W, GM=48 x GN=128, 4 warps, 4 CTA/SM ---
#define SA_IDX(buf, part, row, col) ((((buf) * 2 + (part)) * GM + (row)) * SA_LD + (col))
#define SB_IDX(buf, part, row, col) (SB_BASE + (((buf) * 2 + (part)) * GK + (row)) * SB_LD + (col))

__global__ void __launch_bounds__(128, 4) k_gemm_bf16() {
    extern __shared__ __nv_bfloat16 smem[];

    int tid = threadIdx.x;
    int bx = blockIdx.x;      // N tile (8)
    int by = blockIdx.y;      // M tile (3)
    int bz = blockIdx.z;      // K split (16)
    int m0 = by * GM;
    int n0 = bx * GN;
    int k0 = bz * KLEN;

    int wn = tid >> 5;        // 4 warps in N (32 cols each)

    wmma::fragment<wmma::accumulator, 16, 16, 16, float> acc[3][2];
    #pragma unroll
    for (int m = 0; m < 3; m++)
        #pragma unroll
        for (int n = 0; n < 2; n++)
            wmma::fill_fragment(acc[m][n], 0.f);

    auto load_chunk = [&](int buf, int kg) {
        // A: 2 parts x 48 rows x 4 float4 = 384 cp16; 3 per thread
        #pragma unroll
        for (int i = 0; i < 3; i++) {
            int idx = tid + 128 * i;
            int part = idx / 192;
            int j = idx % 192;
            int row = j >> 2;
            int col = (j & 3) << 3;
            const __nv_bfloat16* src =
                (part ? g_Alo : g_Ahi) + (size_t)(m0 + row) * KD + kg + col;
            cp16(&smem[SA_IDX(buf, part, row, col)], src);
        }
        // B: 2 parts x 32 rows x 16 float4 = 1024 cp16; 8 per thread
        #pragma unroll
        for (int i = 0; i < 8; i++) {
            int idx = tid + 128 * i;
            int part = idx >> 9;
            int j = idx & 511;
            int row = j >> 4;
            int col = (j & 15) << 3;
            const __nv_bfloat16* src =
                (part ? g_Wlo : g_Whi) + (size_t)(kg + row) * HID + n0 + col;
            cp16(&smem[SB_IDX(buf, part, row, col)], src);
        }
    };

    load_chunk(0, k0);
    cp_commit();

    for (int ch = 0; ch < NCH; ch++) {
        if (ch + 1 < NCH) {
            load_chunk((ch + 1) & 1, k0 + (ch + 1) * GK);
            cp_commit();
            cp_wait<1>();
        } else {
            cp_wait<0>();
        }
        __syncthreads();
        int buf = ch & 1;
        #pragma unroll
        for (int ks = 0; ks < GK; ks += 16) {
            wmma::fragment<wmma::matrix_a, 16, 16, 16, __nv_bfloat16, wmma::row_major> afh[3], afl[3];
            #pragma unroll
            for (int m = 0; m < 3; m++) {
                wmma::load_matrix_sync(afh[m], &smem[SA_IDX(buf, 0, m * 16, ks)], SA_LD);
                wmma::load_matrix_sync(afl[m], &smem[SA_IDX(buf, 1, m * 16, ks)], SA_LD);
            }
            #pragma unroll
            for (int n = 0; n < 2; n++) {
                wmma::fragment<wmma::matrix_b, 16, 16, 16, __nv_bfloat16, wmma::row_major> bfh, bfl;
                wmma::load_matrix_sync(bfh, &smem[SB_IDX(buf, 0, ks, wn * 32 + n * 16)], SB_LD);
                wmma::load_matrix_sync(bfl, &smem[SB_IDX(buf, 1, ks, wn * 32 + n * 16)], SB_LD);
                #pragma unroll
                for (int m = 0; m < 3; m++) {
                    wmma::mma_sync(acc[m][n], afh[m], bfh, acc[m][n]);
                    wmma::mma_sync(acc[m][n], afl[m], bfh, acc[m][n]);
                    wmma::mma_sync(acc[m][n], afh[m], bfl, acc[m][n]);
                }
            }
        }
        __syncthreads();
    }

    #pragma unroll
    for (int m = 0; m < 3; m++) {
        #pragma unroll
        for (int n = 0; n < 2; n++) {
            float* outp = g_Gsplit + (size_t)bz * GSPLIT_STRIDE
                        + (size_t)(m0 + m * 16) * HID + n0 + wn * 32 + n * 16;
            wmma::store_matrix_sync(outp, acc[m][n], HID, wmma::mem_row_major);
        }
    }
}

// ---------------- K2: split-K reduce + gs1/gs2 row dots --------------------
__global__ void __launch_bounds__(256) k_reduce_gs(const float* __restrict__ a) {
    int m = blockIdx.x;            // 0..131
    int t = threadIdx.x;           // 256
    float s1 = 0.f, s2 = 0.f;
    for (int c = t; c < HID; c += 256) {
        float s = 0.f;
        #pragma unroll
        for (int z = 0; z < SPLITK; z++)
            s += g_Gsplit[(size_t)z * GSPLIT_STRIDE + m * HID + c];
        g_G[m * HID + c] = s;
        s1 += s * a[c];
        s2 += s * a[HID + c];
    }
    __shared__ float sh1[256], sh2[256];
    sh1[t] = s1; sh2[t] = s2;
    __syncthreads();
    for (int s = 128; s > 0; s >>= 1) {
        if (t < s) { sh1[t] += sh1[t + s]; sh2[t] += sh2[t + s]; }
        __syncthreads();
    }
    if (t == 0) { g_gs1[m] = sh1[0]; g_gs2[m] = sh2[0]; }
}

// ---------------- K3: scatter winners (last edge wins) + amax --------------
__global__ void k_scatter(const int* __restrict__ er, const int* __restrict__ ec) {
    int e = blockIdx.x * blockDim.x + threadIdx.x;
    if (e < NE) atomicMax(&g_winner[er[e] * N_NODES + ec[e]], e);
}
__global__ void k_amax(const int* __restrict__ er, const int* __restrict__ ec,
                       const float* __restrict__ av) {
    int e = blockIdx.x * blockDim.x + threadIdx.x;
    if (e < NE && g_winner[er[e] * N_NODES + ec[e]] == e)
        atomicMax(&g_amax_bits, __float_as_uint(av[e]));   // av >= 0
}

// ---------------- K4: per-row softmax + new_adj + P ----------------
__global__ void __launch_bounds__(128) k_row(const float* __restrict__ adj_vals,
                                             float* __restrict__ out) {
    int r = blockIdx.x;
    int t = threadIdx.x;            // 128
    __shared__ float red[128];

    float s1r = g_gs1[r & 127] + g_gs1[128 + (r >> 7)];

    float ev[4]; int w[4];
    float lmax = -1e30f;
    #pragma unroll
    for (int j = 0; j < 4; j++) {
        int c = t + 128 * j;
        float s2c = g_gs2[c & 127] + g_gs2[128 + j];
        int ww = g_winner[r * N_NODES + c];
        w[j] = ww;
        float x = 0.f;
        if (ww >= 0) { float v = s1r + s2c; x = v > 0.f ? v : 0.2f * v; }
        ev[j] = x;
        lmax = fmaxf(lmax, x);
    }
    red[t] = lmax; __syncthreads();
    for (int s = 64; s > 0; s >>= 1) {
        if (t < s) red[t] = fmaxf(red[t], red[t + s]);
        __syncthreads();
    }
    float rmax = red[0]; __syncthreads();

    float ex[4]; float lsum = 0.f;
    #pragma unroll
    for (int j = 0; j < 4; j++) { ex[j] = expf(ev[j] - rmax); lsum += ex[j]; }
    red[t] = lsum; __syncthreads();
    for (int s = 64; s > 0; s >>= 1) {
        if (t < s) red[t] += red[t + s];
        __syncthreads();
    }
    float inv = 1.f / red[0]; __syncthreads();

    float amax2 = 2.f * __uint_as_float(g_amax_bits);
    float invA = amax2 > 0.f ? 1.f / amax2 : 0.f;

    float attj[4]; float pm = 0.f;
    #pragma unroll
    for (int j = 0; j < 4; j++) {
        float att = ex[j] * inv;
        attj[j] = att;
        float adjn = (w[j] >= 0) ? (2.f * adj_vals[w[j]]) * invA : 0.f;
        out[r * N_NODES + t + 128 * j] = att * adjn;
        pm += att;
    }
    g_P[r * MG + t] = pm;          // c & 127 == t for all 4 cols

    #pragma unroll
    for (int j = 0; j < 4; j++) {  // column-block sums -> P[r, 128+j]
        red[t] = attj[j]; __syncthreads();
        for (int s = 64; s > 0; s >>= 1) {
            if (t < s) red[t] += red[t + s];
            __syncthreads();
        }
        if (t == 0) g_P[r * MG + 128 + j] = red[0];
        __syncthreads();
    }
}

// ---------------- K5: hp = P(512,132) @ G(132,1024) ----------------
__global__ void __launch_bounds__(256) k_hp() {
    __shared__ float Ps[32][MG];
    __shared__ float Gs[MG][32];
    int bx = blockIdx.x;            // col tile (32)
    int by = blockIdx.y;            // row tile (16)
    int tid = threadIdx.x;

    for (int i = tid; i < 32 * MG; i += 256) {
        int rr = i / MG, kk = i % MG;
        Ps[rr][kk] = g_P[(by * 32 + rr) * MG + kk];
    }
    for (int i = tid; i < MG * 32; i += 256) {
        int kk = i / 32, cc = i % 32;
        Gs[kk][cc] = g_G[kk * HID + bx * 32 + cc];
    }
    __syncthreads();

    int tx = tid & 7, ty = tid >> 3;   // ty: row 0..31, tx: col4 0..7
    float4 acc = make_float4(0.f, 0.f, 0.f, 0.f);
    #pragma unroll 4
    for (int k = 0; k < MG; k++) {
        float p = Ps[ty][k];
        float4 gv = *(float4*)&Gs[k][tx * 4];
        acc.x += p * gv.x; acc.y += p * gv.y;
        acc.z += p * gv.z; acc.w += p * gv.w;
    }
    int row = by * 32 + ty, col = bx * 32 + tx * 4;
    *(float4*)&g_hp[row * HID + col] = acc;
}

// ---------------- K6: gemv, RG=2 rows per block ----------------
__global__ void __launch_bounds__(256) k_gemv(const float* __restrict__ lin_w) {
    int chunk = blockIdx.x;          // 0..CH-1
    int rg = blockIdx.y;             // 0..NRG-1
    int t = threadIdx.x;             // 256
    int row0 = rg * RG;
    int r0 = row0 < NOUT ? row0 : NOUT - 1;
    int r1 = row0 + 1 < NOUT ? row0 + 1 : NOUT - 1;

    const float4* w0 = (const float4*)(lin_w + (size_t)r0 * HPLEN + (size_t)chunk * CHLEN);
    const float4* w1 = (const float4*)(lin_w + (size_t)r1 * HPLEN + (size_t)chunk * CHLEN);
    const float4* vp = (const float4*)(g_hp + (size_t)chunk * CHLEN);

    float a0 = 0.f, a1 = 0.f;
    #pragma unroll 4
    for (int i = t; i < CHLEN / 4; i += 256) {
        float4 v = __ldg(&vp[i]);
        float4 x = __ldcs(&w0[i]);
        float4 y = __ldcs(&w1[i]);
        a0 += x.x * v.x + x.y * v.y + x.z * v.z + x.w * v.w;
        a1 += y.x * v.x + y.y * v.y + y.z * v.z + y.w * v.w;
    }

    __shared__ float sh[2][256];
    sh[0][t] = a0; sh[1][t] = a1;
    __syncthreads();
    for (int s = 128; s > 0; s >>= 1) {
        if (t < s) { sh[0][t] += sh[0][t + s]; sh[1][t] += sh[1][t + s]; }
        __syncthreads();
    }
    if (t < RG) {
        int row = row0 + t;
        if (row < NOUT) g_partial[row * CH + chunk] = sh[t][0];
    }
}

// ---------------- K7: finalize + min/max normalize ----------------
__global__ void k_final(const float* __restrict__ lin_b, float* __restrict__ out) {
    __shared__ float vals[NOUT];
    __shared__ float smin[256], smax[256];
    int t = threadIdx.x;            // 256
    for (int i = t; i < NOUT; i += 256) {
        float s = lin_b[i];
        #pragma unroll
        for (int c = 0; c < CH; c++) s += g_partial[i * CH + c];
        vals[i] = s;
    }
    __syncthreads();
    float mn = 1e30f, mx = -1e30f;
    for (int i = t; i < NOUT; i += 256) {
        mn = fminf(mn, vals[i]);
        mx = fmaxf(mx, vals[i]);
    }
    smin[t] = mn; smax[t] = mx; __syncthreads();
    for (int s = 128; s > 0; s >>= 1) {
        if (t < s) {
            smin[t] = fminf(smin[t], smin[t + s]);
            smax[t] = fmaxf(smax[t], smax[t + s]);
        }
        __syncthreads();
    }
    float gmn = smin[0], gmx = smax[0];
    float denom = gmx - gmn;
    for (int i = t; i < NOUT; i += 256)
        out[NN + i] = (denom == 0.f) ? 0.5f : (vals[i] - gmn) / denom;
}

// ---------------- launch ----------------
extern "C" void kernel_launch(void* const* d_in, const int* in_sizes, int n_in,
                              void* d_out, int out_size) {
    const float* img = (const float*)d_in[0];
    const int*   er  = (const int*)d_in[1];
    const int*   ec  = (const int*)d_in[2];
    const float* av  = (const float*)d_in[3];
    const float* X   = (const float*)d_in[4];
    const float* W   = (const float*)d_in[5];
    const float* a   = (const float*)d_in[6];
    const float* lw  = (const float*)d_in[7];
    const float* lb  = (const float*)d_in[8];
    float* out = (float*)d_out;

    static cudaStream_t s2 = []() {
        cudaStream_t s; cudaStreamCreateWithFlags(&s, cudaStreamNonBlocking); return s;
    }();
    static cudaEvent_t e0 = []() {
        cudaEvent_t e; cudaEventCreateWithFlags(&e, cudaEventDisableTiming); return e;
    }();
    static cudaEvent_t e1 = []() {
        cudaEvent_t e; cudaEventCreateWithFlags(&e, cudaEventDisableTiming); return e;
    }();
    static bool attr_set = []() {
        cudaFuncSetAttribute(k_gemm_bf16, cudaFuncAttributeMaxDynamicSharedMemorySize,
                             GEMM_SMEM_BYTES);
        return true;
    }();
    (void)attr_set;

    void* winner_ptr = nullptr;
    void* amax_ptr = nullptr;
    cudaGetSymbolAddress(&winner_ptr, g_winner);
    cudaGetSymbolAddress(&amax_ptr, g_amax_bits);

    // fork: edge path on s2
    cudaEventRecord(e0, 0);
    cudaStreamWaitEvent(s2, e0, 0);
    cudaMemsetAsync(winner_ptr, 0xFF, NN * sizeof(int), s2);        // winner = -1
    cudaMemsetAsync(amax_ptr, 0x00, sizeof(unsigned int), s2);      // amax = 0
    k_scatter<<<64, 256, 0, s2>>>(er, ec);
    k_amax<<<64, 256, 0, s2>>>(er, ec, av);
    cudaEventRecord(e1, s2);

    // main path on default stream
    int prep_blocks = (NW4 + NA4 + 255) / 256;
    k_prep<<<prep_blocks, 256>>>(W, X, img);
    dim3 g1(8, 3, SPLITK);
    k_gemm_bf16<<<g1, 128, GEMM_SMEM_BYTES>>>();
    k_reduce_gs<<<MG, 256>>>(a);

    // join
    cudaStreamWaitEvent(0, e1, 0);
    k_row<<<512, 128>>>(av, out);
    dim3 g5(32, 16);
    k_hp<<<g5, 256>>>();
    dim3 g6(CH, NRG);
    k_gemv<<<g6, 256>>>(lw);
    k_final<<<1, 256>>>(lb, out);
}